// round 12
// baseline (speedup 1.0000x reference)
#include <cuda_runtime.h>
#include <cuda_fp16.h>
#include <cstdint>

#define B_   4
#define S_   256
#define H_   768
#define NTOT 3840   // 5*768 : 4 basis slots + self slot
#define KW   1024   // 4*256 : step-2 K (4 c-blocks of 256)

// ---------------- static device scratch -------------------------------------
__device__ __align__(256) __half g_h[B_ * S_ * H_];      // hidden fp16 [1024][768]
__device__ __align__(256) __half g_bas[4 * H_ * H_];     // basic fp16 [c][h][o]
__device__ __align__(256) __half g_self[H_ * H_];        // selfw^T fp16 [h][o]
__device__ __align__(256) __half g_W[B_ * S_ * KW];      // W [b][i][c*256+j]
__device__ __align__(256) __half g_hb[B_ * S_ * NTOT];   // hb [b][s][n] (slots 0-3 used)
__device__ __align__(256) int    g_relsT[B_ * S_ * S_];  // rels transposed

// ---------------- helpers ---------------------------------------------------
__device__ __forceinline__ uint32_t s2u(const void* p) {
    uint32_t a;
    asm("{ .reg .u64 t; cvta.to.shared.u64 t, %1; cvt.u32.u64 %0, t; }"
        : "=r"(a) : "l"(p));
    return a;
}
__device__ __forceinline__ void cp16(uint32_t dst, const void* src) {
    asm volatile("cp.async.cg.shared.global [%0], [%1], 16;"
                 :: "r"(dst), "l"(src) : "memory");
}
__device__ __forceinline__ void ldsm4(uint32_t* r, uint32_t addr) {
    asm volatile("ldmatrix.sync.aligned.m8n8.x4.shared.b16 {%0,%1,%2,%3}, [%4];"
                 : "=r"(r[0]), "=r"(r[1]), "=r"(r[2]), "=r"(r[3]) : "r"(addr));
}
__device__ __forceinline__ void ldsm4t(uint32_t* r, uint32_t addr) {
    asm volatile("ldmatrix.sync.aligned.m8n8.x4.trans.shared.b16 {%0,%1,%2,%3}, [%4];"
                 : "=r"(r[0]), "=r"(r[1]), "=r"(r[2]), "=r"(r[3]) : "r"(addr));
}
__device__ __forceinline__ void mma_f16(float* d, const uint32_t* a,
                                        uint32_t b0, uint32_t b1) {
    asm volatile("mma.sync.aligned.m16n8k16.row.col.f32.f16.f16.f32 "
                 "{%0,%1,%2,%3}, {%4,%5,%6,%7}, {%8,%9}, {%0,%1,%2,%3};"
                 : "+f"(d[0]), "+f"(d[1]), "+f"(d[2]), "+f"(d[3])
                 : "r"(a[0]), "r"(a[1]), "r"(a[2]), "r"(a[3]), "r"(b0), "r"(b1));
}
// fire-and-forget vector reduction (sm_90+)
__device__ __forceinline__ void red2(float* p, float x, float y) {
    asm volatile("red.global.add.v2.f32 [%0], {%1, %2};"
                 :: "l"(p), "f"(x), "f"(y) : "memory");
}

// ---------------- GEMM geometry ----------------------------------------------
// A: rows of 64B (32 halves, one 32-K chunk), pitch 80 -> conflict-free ldsm.
// B: 32 k-rows, pitch 272 (128n) / 144 (64n) -> conflict-free trans ldsm.
#define A_PITCH 80
#define HB_BP   272
#define HB_ABUF (64 * A_PITCH)               // 5120
#define HB_BBUF (32 * HB_BP)                 // 8704
#define HB_STG  (HB_ABUF + HB_BBUF)          // 13824
#define OUT_BP   144
#define OUT_BBUF (32 * OUT_BP)               // 4608
#define OUT_STG  (HB_ABUF + OUT_BBUF)        // 9728

__device__ __forceinline__ void ld_a32(const __half* __restrict__ src, int ld,
                                       uint32_t s, int t) {
    #pragma unroll
    for (int u = 0; u < 2; u++) {
        const int id = t + 128 * u;
        const int r = id >> 2, seg = id & 3;
        cp16(s + r * A_PITCH + seg * 16, src + (size_t)r * ld + seg * 8);
    }
}
template<int NCOLS, int BP>
__device__ __forceinline__ void ld_b32(const __half* __restrict__ src, int ld,
                                       uint32_t s, int t) {
    #pragma unroll
    for (int u = 0; u < 32 * (NCOLS / 8) / 128; u++) {
        const int id = t + 128 * u;
        const int k = id / (NCOLS / 8), q = id % (NCOLS / 8);
        cp16(s + k * BP + q * 16, src + (size_t)k * ld + q * 8);
    }
}

// One 16-K sub-chunk, trans-B. Warp tile 32 x (NG*16).
template<int BP, int NG>
__device__ __forceinline__ void sub_t(uint32_t a_s, uint32_t b_s,
                                      float acc[2][NG * 2][4],
                                      int lane, int wm, int wn)
{
    const int arow = wm * 32 + (lane & 15);
    const uint32_t abase = a_s + (uint32_t)arow * A_PITCH + (uint32_t)(lane >> 4) * 16;
    uint32_t ah[2][4], bh[NG][4];
    ldsm4(ah[0], abase);
    ldsm4(ah[1], abase + 16 * A_PITCH);
    const int krow = (lane & 7) | ((lane >> 1) & 8);
    const int noff = (lane & 8) ? 16 : 0;
    #pragma unroll
    for (int g = 0; g < NG; g++)
        ldsm4t(bh[g], b_s + (uint32_t)krow * BP + (uint32_t)(wn * (NG * 32) + g * 32) + noff);
    #pragma unroll
    for (int mt = 0; mt < 2; mt++)
        #pragma unroll
        for (int g = 0; g < NG; g++)
            #pragma unroll
            for (int s = 0; s < 2; s++)
                mma_f16(acc[mt][g * 2 + s], ah[mt], bh[g][s], bh[g][s + 2]);
}

// ---------------------------------------------------------------------------
// Fused prep: cvt hidden | cvt basic | transpose selfw | transpose rels.
// ---------------------------------------------------------------------------
#define NB_H    768
#define NB_BAS  2304
#define NB_SELF 576
#define NB_RELS 256

__global__ __launch_bounds__(256) void prep_kernel(
    const float* __restrict__ hidden, const float* __restrict__ basic,
    const float* __restrict__ selfw, const int* __restrict__ rels)
{
    const int blk = blockIdx.x;
    const int t = threadIdx.x;
    if (blk < NB_H + NB_BAS) {
        const float* src; __half* dst; int i;
        if (blk < NB_H) { src = hidden; dst = g_h; i = blk * 256 + t; }
        else            { src = basic;  dst = g_bas; i = (blk - NB_H) * 256 + t; }
        float4 v = reinterpret_cast<const float4*>(src)[i];
        reinterpret_cast<__half2*>(dst)[i * 2]     = __floats2half2_rn(v.x, v.y);
        reinterpret_cast<__half2*>(dst)[i * 2 + 1] = __floats2half2_rn(v.z, v.w);
    } else if (blk < NB_H + NB_BAS + NB_SELF) {
        __shared__ float tile[32][33];
        const int tl = blk - (NB_H + NB_BAS);
        const int h0 = (tl % 24) * 32, o0 = (tl / 24) * 32;
        const int tx = t & 31, ty = t >> 5;
        #pragma unroll
        for (int r = 0; r < 4; r++)
            tile[ty + 8 * r][tx] = selfw[(size_t)(o0 + ty + 8 * r) * H_ + h0 + tx];
        __syncthreads();
        #pragma unroll
        for (int r = 0; r < 4; r++)
            g_self[(size_t)(h0 + ty + 8 * r) * H_ + o0 + tx] =
                __float2half(tile[tx][ty + 8 * r]);
    } else {
        __shared__ int tile[32][33];
        const int id = blk - (NB_H + NB_BAS + NB_SELF);
        const int b = id >> 6, tl = id & 63;
        const int j0 = (tl & 7) * 32, i0 = (tl >> 3) * 32;
        const int tx = t & 31, ty = t >> 5;
        #pragma unroll
        for (int r = 0; r < 4; r++)
            tile[ty + 8 * r][tx] = rels[((size_t)b * S_ + i0 + ty + 8 * r) * S_ + j0 + tx];
        __syncthreads();
        #pragma unroll
        for (int r = 0; r < 4; r++)
            g_relsT[((size_t)b * S_ + j0 + ty + 8 * r) * S_ + i0 + tx] = tile[tx][ty + 8 * r];
    }
}

// ---------------------------------------------------------------------------
// build_w: histogram + W[b][i][c*256+j] fp16. All reads coalesced.
// ---------------------------------------------------------------------------
__global__ void build_w_kernel(const int* __restrict__ rels,
                               const float* __restrict__ rel_weight) {
    const int bi = blockIdx.x;
    const int b = bi >> 8;
    const int i = bi & 255;
    const int t = threadIdx.x;

    __shared__ int   cf[32], cr[32];
    __shared__ float inv_f[32], inv_r[32];
    __shared__ float rw[64 * 4];

    if (t < 32) { cf[t] = 0; cr[t] = 0; }
    rw[t] = rel_weight[t];
    __syncthreads();

    const int lf = rels[(b * S_ + i) * S_ + t];
    const int lr = g_relsT[(b * S_ + i) * S_ + t];
    if (lf > 0) atomicAdd(&cf[lf], 1);
    if (lr > 0) atomicAdd(&cr[lr], 1);
    __syncthreads();

    if (t < 32) {
        inv_f[t] = 1.0f / (float)(cf[t] > 0 ? cf[t] : 1);
        inv_r[t] = 1.0f / (float)(cr[t] > 0 ? cr[t] : 1);
    }
    __syncthreads();

    float w[4] = {0.f, 0.f, 0.f, 0.f};
    if (lf > 0) {
        const float s = inv_f[lf];
        #pragma unroll
        for (int c = 0; c < 4; c++) w[c] += rw[lf * 4 + c] * s;
    }
    if (lr > 0) {
        const float s = inv_r[lr];
        #pragma unroll
        for (int c = 0; c < 4; c++) w[c] += rw[(lr + 32) * 4 + c] * s;
    }
    #pragma unroll
    for (int c = 0; c < 4; c++)
        g_W[((size_t)(b * S_ + i)) * KW + c * 256 + t] = __float2half(w[c]);
}

// ---------------------------------------------------------------------------
// GEMM-HB: hb (1024x3840) = g_h (1024x768) @ [basic|selfT] (768x3840)
// grid (30, 16) = 480 CTAs, 128 thr, CTA 64x128, NC=24, 3-stage.
// cslot<4: write fp16 hb. cslot==4 (self term): write fp32 base of `out`.
// ---------------------------------------------------------------------------
__global__ __launch_bounds__(128, 4) void gemm_hb_kernel(float* __restrict__ out) {
    __shared__ __align__(128) char sm[3 * HB_STG];
    const int n0 = blockIdx.x * 128;     // never straddles a 768-slot
    const int m0 = blockIdx.y * 64;      // global row in [0,1024)
    const int cslot = n0 / 768;
    const int o0 = n0 - cslot * 768;

    const __half* A  = g_h + (size_t)m0 * H_;
    const __half* Bm = (cslot < 4) ? g_bas + (size_t)cslot * H_ * H_ + o0
                                   : g_self + o0;

    const int t = threadIdx.x, lane = t & 31, wid = t >> 5;
    const int wm = wid & 1, wn = wid >> 1;
    const uint32_t smb = s2u(sm);

    float acc[2][8][4] = {};
    const int NC = 24;
    #pragma unroll 1
    for (int p = 0; p < 2; p++) {
        const int k0 = p * 32;
        const uint32_t st = smb + (uint32_t)p * HB_STG;
        ld_a32(A + k0, H_, st, t);
        ld_b32<128, HB_BP>(Bm + (size_t)k0 * H_, H_, st + HB_ABUF, t);
        asm volatile("cp.async.commit_group;" ::: "memory");
    }
    for (int c = 0; c < NC; c++) {
        asm volatile("cp.async.wait_group 1;" ::: "memory");
        __syncthreads();
        const uint32_t st = smb + (uint32_t)(c % 3) * HB_STG;
        sub_t<HB_BP, 4>(st, st + HB_ABUF, acc, lane, wm, wn);
        sub_t<HB_BP, 4>(st + 32, st + HB_ABUF + 16 * HB_BP, acc, lane, wm, wn);
        if (c + 2 < NC) {
            const int k0 = (c + 2) * 32;
            const uint32_t sn = smb + (uint32_t)((c + 2) % 3) * HB_STG;
            ld_a32(A + k0, H_, sn, t);
            ld_b32<128, HB_BP>(Bm + (size_t)k0 * H_, H_, sn + HB_ABUF, t);
        }
        asm volatile("cp.async.commit_group;" ::: "memory");
    }

    if (cslot < 4) {
        #pragma unroll
        for (int mt = 0; mt < 2; mt++)
            #pragma unroll
            for (int nv = 0; nv < 8; nv++) {
                const int row = m0 + wm * 32 + mt * 16 + (lane >> 2);
                const int col = n0 + wn * 64 + nv * 8 + (lane & 3) * 2;
                *reinterpret_cast<__half2*>(g_hb + (size_t)row * NTOT + col) =
                    __floats2half2_rn(acc[mt][nv][0], acc[mt][nv][1]);
                *reinterpret_cast<__half2*>(g_hb + (size_t)(row + 8) * NTOT + col) =
                    __floats2half2_rn(acc[mt][nv][2], acc[mt][nv][3]);
            }
    } else {
        #pragma unroll
        for (int mt = 0; mt < 2; mt++)
            #pragma unroll
            for (int nv = 0; nv < 8; nv++) {
                const int row = m0 + wm * 32 + mt * 16 + (lane >> 2);
                const int col = o0 + wn * 64 + nv * 8 + (lane & 3) * 2;
                float2 v0, v1;
                v0.x = acc[mt][nv][0]; v0.y = acc[mt][nv][1];
                v1.x = acc[mt][nv][2]; v1.y = acc[mt][nv][3];
                *reinterpret_cast<float2*>(out + (size_t)row * H_ + col) = v0;
                *reinterpret_cast<float2*>(out + (size_t)(row + 8) * H_ + col) = v1;
            }
    }
}

// ---------------------------------------------------------------------------
// GEMM-OUT split-K(4): out += W[:, kc*256:+256] @ hb-slot kc, via red.v2.f32.
// grid (12, 16, 4) = 768 CTAs, 128 thr, CTA 64x64, warp 32x32, NC=8, 3-stage.
// ---------------------------------------------------------------------------
__global__ __launch_bounds__(128, 4) void gemm_out_kernel(float* __restrict__ out) {
    __shared__ __align__(128) char sm[3 * OUT_STG];
    const int n0 = blockIdx.x * 64;
    const int row0 = blockIdx.y * 64;        // global row in [0,1024)
    const int kc = blockIdx.z;               // 0..3
    const int b = row0 >> 8;

    const __half* A  = g_W + (size_t)row0 * KW + kc * 256;
    const __half* Bm = g_hb + (size_t)b * S_ * NTOT + (size_t)kc * 768 + n0;  // ld NTOT

    const int t = threadIdx.x, lane = t & 31, wid = t >> 5;
    const int wm = wid & 1, wn = wid >> 1;
    const uint32_t smb = s2u(sm);

    float acc[2][4][4] = {};
    const int NC = 8;
    #pragma unroll 1
    for (int p = 0; p < 2; p++) {
        const int k0 = p * 32;
        const uint32_t st = smb + (uint32_t)p * OUT_STG;
        ld_a32(A + k0, KW, st, t);
        ld_b32<64, OUT_BP>(Bm + (size_t)k0 * NTOT, NTOT, st + HB_ABUF, t);
        asm volatile("cp.async.commit_group;" ::: "memory");
    }
    for (int c = 0; c < NC; c++) {
        asm volatile("cp.async.wait_group 1;" ::: "memory");
        __syncthreads();
        const uint32_t st = smb + (uint32_t)(c % 3) * OUT_STG;
        sub_t<OUT_BP, 2>(st, st + HB_ABUF, acc, lane, wm, wn);
        sub_t<OUT_BP, 2>(st + 32, st + HB_ABUF + 16 * OUT_BP, acc, lane, wm, wn);
        if (c + 2 < NC) {
            const int k0 = (c + 2) * 32;
            const uint32_t sn = smb + (uint32_t)((c + 2) % 3) * OUT_STG;
            ld_a32(A + k0, KW, sn, t);
            ld_b32<64, OUT_BP>(Bm + (size_t)k0 * NTOT, NTOT, sn + HB_ABUF, t);
        }
        asm volatile("cp.async.commit_group;" ::: "memory");
    }

    // epilogue: vector fire-and-forget reductions onto the fp32 base.
    #pragma unroll
    for (int mt = 0; mt < 2; mt++)
        #pragma unroll
        for (int nv = 0; nv < 4; nv++) {
            const int row = row0 + wm * 32 + mt * 16 + (lane >> 2);
            const int col = n0 + wn * 32 + nv * 8 + (lane & 3) * 2;
            red2(out + (size_t)row * H_ + col,       acc[mt][nv][0], acc[mt][nv][1]);
            red2(out + (size_t)(row + 8) * H_ + col, acc[mt][nv][2], acc[mt][nv][3]);
        }
}

// ---------------------------------------------------------------------------
extern "C" void kernel_launch(void* const* d_in, const int* in_sizes, int n_in,
                              void* d_out, int out_size) {
    const float* hidden     = (const float*)d_in[0]; // [4,256,768]
    const int*   rels       = (const int*)  d_in[1]; // [4,256,256]
    const float* basic      = (const float*)d_in[2]; // [4,768,768]
    const float* rel_weight = (const float*)d_in[3]; // [64,4]
    const float* self_w     = (const float*)d_in[4]; // [768,768] (out,in)
    float* out = (float*)d_out;                      // [4,256,768]

    prep_kernel<<<NB_H + NB_BAS + NB_SELF + NB_RELS, 256>>>(hidden, basic, self_w, rels);
    build_w_kernel<<<B_ * S_, 256>>>(rels, rel_weight);
    gemm_hb_kernel<<<dim3(NTOT / 128, (B_ * S_) / 64), 128>>>(out);
    gemm_out_kernel<<<dim3(H_ / 64, (B_ * S_) / 64, 4), 128>>>(out);
}

// round 13
// speedup vs baseline: 1.0094x; 1.0094x over previous
#include <cuda_runtime.h>
#include <cuda_fp16.h>
#include <cstdint>

#define B_   4
#define S_   256
#define H_   768
#define NTOT 3840   // 5*768 : 4 basis slots + self slot
#define KW   1024   // 4*256 : step-2 K (4 c-blocks of 256)

// ---------------- static device scratch -------------------------------------
__device__ __align__(256) __half g_h[B_ * S_ * H_];      // hidden fp16 [1024][768]
__device__ __align__(256) __half g_bas[4 * H_ * H_];     // basic fp16 [c][h][o]
__device__ __align__(256) __half g_self[H_ * H_];        // selfw^T fp16 [h][o]
__device__ __align__(256) __half g_W[B_ * S_ * KW];      // W [b][i][c*256+j]
__device__ __align__(256) __half g_hb2[4 * B_ * S_ * H_];// hb slot-major [slot][1024][768]
__device__ __align__(256) int    g_relsT[B_ * S_ * S_];  // rels transposed

// ---------------- helpers ---------------------------------------------------
__device__ __forceinline__ uint32_t s2u(const void* p) {
    uint32_t a;
    asm("{ .reg .u64 t; cvta.to.shared.u64 t, %1; cvt.u32.u64 %0, t; }"
        : "=r"(a) : "l"(p));
    return a;
}
__device__ __forceinline__ void cp16(uint32_t dst, const void* src) {
    asm volatile("cp.async.cg.shared.global [%0], [%1], 16;"
                 :: "r"(dst), "l"(src) : "memory");
}
__device__ __forceinline__ void ldsm4(uint32_t* r, uint32_t addr) {
    asm volatile("ldmatrix.sync.aligned.m8n8.x4.shared.b16 {%0,%1,%2,%3}, [%4];"
                 : "=r"(r[0]), "=r"(r[1]), "=r"(r[2]), "=r"(r[3]) : "r"(addr));
}
__device__ __forceinline__ void ldsm4t(uint32_t* r, uint32_t addr) {
    asm volatile("ldmatrix.sync.aligned.m8n8.x4.trans.shared.b16 {%0,%1,%2,%3}, [%4];"
                 : "=r"(r[0]), "=r"(r[1]), "=r"(r[2]), "=r"(r[3]) : "r"(addr));
}
__device__ __forceinline__ void mma_f16(float* d, const uint32_t* a,
                                        uint32_t b0, uint32_t b1) {
    asm volatile("mma.sync.aligned.m16n8k16.row.col.f32.f16.f16.f32 "
                 "{%0,%1,%2,%3}, {%4,%5,%6,%7}, {%8,%9}, {%0,%1,%2,%3};"
                 : "+f"(d[0]), "+f"(d[1]), "+f"(d[2]), "+f"(d[3])
                 : "r"(a[0]), "r"(a[1]), "r"(a[2]), "r"(a[3]), "r"(b0), "r"(b1));
}
// fire-and-forget vector reduction (sm_90+)
__device__ __forceinline__ void red2(float* p, float x, float y) {
    asm volatile("red.global.add.v2.f32 [%0], {%1, %2};"
                 :: "l"(p), "f"(x), "f"(y) : "memory");
}

// ---------------- unified GEMM geometry --------------------------------------
// CTA tile 64(M) x 128(N), 128 threads = 4 warps, warp tile 32x64.
// K-chunk 32, 3-stage. A: pitch 80 (conflict-free ldsm). B: 32 k-rows,
// pitch 272 (conflict-free trans ldsm).
#define A_PITCH 80
#define G_BP    272
#define G_ABUF  (64 * A_PITCH)              // 5120
#define G_BBUF  (32 * G_BP)                 // 8704
#define G_STG   (G_ABUF + G_BBUF)           // 13824

__device__ __forceinline__ void ld_a32(const __half* __restrict__ src, int ld,
                                       uint32_t s, int t) {
    #pragma unroll
    for (int u = 0; u < 2; u++) {
        const int id = t + 128 * u;
        const int r = id >> 2, seg = id & 3;
        cp16(s + r * A_PITCH + seg * 16, src + (size_t)r * ld + seg * 8);
    }
}
__device__ __forceinline__ void ld_b32(const __half* __restrict__ src, int ld,
                                       uint32_t s, int t) {
    #pragma unroll
    for (int u = 0; u < 4; u++) {
        const int id = t + 128 * u;
        const int k = id >> 4, q = id & 15;
        cp16(s + k * G_BP + q * 16, src + (size_t)k * ld + q * 8);
    }
}

// One 16-K sub-chunk. wm,wn in {0,1}; 64 n per warp.
__device__ __forceinline__ void sub_t4(uint32_t a_s, uint32_t b_s,
                                       float acc[2][8][4],
                                       int lane, int wm, int wn)
{
    const int arow = wm * 32 + (lane & 15);
    const uint32_t abase = a_s + (uint32_t)arow * A_PITCH + (uint32_t)(lane >> 4) * 16;
    uint32_t ah[2][4], bh[4][4];
    ldsm4(ah[0], abase);
    ldsm4(ah[1], abase + 16 * A_PITCH);
    const int krow = (lane & 7) | ((lane >> 1) & 8);
    const int noff = (lane & 8) ? 16 : 0;
    #pragma unroll
    for (int g = 0; g < 4; g++)
        ldsm4t(bh[g], b_s + (uint32_t)krow * G_BP + (uint32_t)(wn * 128 + g * 32) + noff);
    #pragma unroll
    for (int mt = 0; mt < 2; mt++)
        #pragma unroll
        for (int g = 0; g < 4; g++)
            #pragma unroll
            for (int s = 0; s < 2; s++)
                mma_f16(acc[mt][g * 2 + s], ah[mt], bh[g][s], bh[g][s + 2]);
}

// ---------------------------------------------------------------------------
// Fused prep: cvt hidden | cvt basic | transpose selfw | transpose rels.
// ---------------------------------------------------------------------------
#define NB_H    768
#define NB_BAS  2304
#define NB_SELF 576
#define NB_RELS 256

__global__ __launch_bounds__(256) void prep_kernel(
    const float* __restrict__ hidden, const float* __restrict__ basic,
    const float* __restrict__ selfw, const int* __restrict__ rels)
{
    const int blk = blockIdx.x;
    const int t = threadIdx.x;
    if (blk < NB_H + NB_BAS) {
        const float* src; __half* dst; int i;
        if (blk < NB_H) { src = hidden; dst = g_h; i = blk * 256 + t; }
        else            { src = basic;  dst = g_bas; i = (blk - NB_H) * 256 + t; }
        float4 v = reinterpret_cast<const float4*>(src)[i];
        reinterpret_cast<__half2*>(dst)[i * 2]     = __floats2half2_rn(v.x, v.y);
        reinterpret_cast<__half2*>(dst)[i * 2 + 1] = __floats2half2_rn(v.z, v.w);
    } else if (blk < NB_H + NB_BAS + NB_SELF) {
        __shared__ float tile[32][33];
        const int tl = blk - (NB_H + NB_BAS);
        const int h0 = (tl % 24) * 32, o0 = (tl / 24) * 32;
        const int tx = t & 31, ty = t >> 5;
        #pragma unroll
        for (int r = 0; r < 4; r++)
            tile[ty + 8 * r][tx] = selfw[(size_t)(o0 + ty + 8 * r) * H_ + h0 + tx];
        __syncthreads();
        #pragma unroll
        for (int r = 0; r < 4; r++)
            g_self[(size_t)(h0 + ty + 8 * r) * H_ + o0 + tx] =
                __float2half(tile[tx][ty + 8 * r]);
    } else {
        __shared__ int tile[32][33];
        const int id = blk - (NB_H + NB_BAS + NB_SELF);
        const int b = id >> 6, tl = id & 63;
        const int j0 = (tl & 7) * 32, i0 = (tl >> 3) * 32;
        const int tx = t & 31, ty = t >> 5;
        #pragma unroll
        for (int r = 0; r < 4; r++)
            tile[ty + 8 * r][tx] = rels[((size_t)b * S_ + i0 + ty + 8 * r) * S_ + j0 + tx];
        __syncthreads();
        #pragma unroll
        for (int r = 0; r < 4; r++)
            g_relsT[((size_t)b * S_ + j0 + ty + 8 * r) * S_ + i0 + tx] = tile[tx][ty + 8 * r];
    }
}

// ---------------------------------------------------------------------------
// build_w: histogram + W[b][i][c*256+j] fp16. All reads coalesced.
// ---------------------------------------------------------------------------
__global__ void build_w_kernel(const int* __restrict__ rels,
                               const float* __restrict__ rel_weight) {
    const int bi = blockIdx.x;
    const int b = bi >> 8;
    const int i = bi & 255;
    const int t = threadIdx.x;

    __shared__ int   cf[32], cr[32];
    __shared__ float inv_f[32], inv_r[32];
    __shared__ float rw[64 * 4];

    if (t < 32) { cf[t] = 0; cr[t] = 0; }
    rw[t] = rel_weight[t];
    __syncthreads();

    const int lf = rels[(b * S_ + i) * S_ + t];
    const int lr = g_relsT[(b * S_ + i) * S_ + t];
    if (lf > 0) atomicAdd(&cf[lf], 1);
    if (lr > 0) atomicAdd(&cr[lr], 1);
    __syncthreads();

    if (t < 32) {
        inv_f[t] = 1.0f / (float)(cf[t] > 0 ? cf[t] : 1);
        inv_r[t] = 1.0f / (float)(cr[t] > 0 ? cr[t] : 1);
    }
    __syncthreads();

    float w[4] = {0.f, 0.f, 0.f, 0.f};
    if (lf > 0) {
        const float s = inv_f[lf];
        #pragma unroll
        for (int c = 0; c < 4; c++) w[c] += rw[lf * 4 + c] * s;
    }
    if (lr > 0) {
        const float s = inv_r[lr];
        #pragma unroll
        for (int c = 0; c < 4; c++) w[c] += rw[(lr + 32) * 4 + c] * s;
    }
    #pragma unroll
    for (int c = 0; c < 4; c++)
        g_W[((size_t)(b * S_ + i)) * KW + c * 256 + t] = __float2half(w[c]);
}

// ---------------------------------------------------------------------------
// GEMM-HB: g_h (1024x768) @ [basic|selfT] (768x3840).
// grid (30, 16) = 480 CTAs, 128 thr, CTA 64x128, NC=24, 3-stage.
// cslot<4: write fp16 into slot-major g_hb2[cslot]. cslot==4: fp32 base of out.
// ---------------------------------------------------------------------------
__global__ __launch_bounds__(128, 4) void gemm_hb_kernel(float* __restrict__ out) {
    __shared__ __align__(128) char sm[3 * G_STG];
    const int n0 = blockIdx.x * 128;     // never straddles a 768-slot
    const int m0 = blockIdx.y * 64;      // global row in [0,1024)
    const int cslot = n0 / 768;
    const int o0 = n0 - cslot * 768;

    const __half* A  = g_h + (size_t)m0 * H_;
    const __half* Bm = (cslot < 4) ? g_bas + (size_t)cslot * H_ * H_ + o0
                                   : g_self + o0;

    const int t = threadIdx.x, lane = t & 31, wid = t >> 5;
    const int wm = wid & 1, wn = wid >> 1;
    const uint32_t smb = s2u(sm);

    float acc[2][8][4] = {};
    const int NC = 24;
    #pragma unroll 1
    for (int p = 0; p < 2; p++) {
        const int k0 = p * 32;
        const uint32_t st = smb + (uint32_t)p * G_STG;
        ld_a32(A + k0, H_, st, t);
        ld_b32(Bm + (size_t)k0 * H_, H_, st + G_ABUF, t);
        asm volatile("cp.async.commit_group;" ::: "memory");
    }
    for (int c = 0; c < NC; c++) {
        asm volatile("cp.async.wait_group 1;" ::: "memory");
        __syncthreads();
        const uint32_t st = smb + (uint32_t)(c % 3) * G_STG;
        sub_t4(st, st + G_ABUF, acc, lane, wm, wn);
        sub_t4(st + 32, st + G_ABUF + 16 * G_BP, acc, lane, wm, wn);
        if (c + 2 < NC) {
            const int k0 = (c + 2) * 32;
            const uint32_t sn = smb + (uint32_t)((c + 2) % 3) * G_STG;
            ld_a32(A + k0, H_, sn, t);
            ld_b32(Bm + (size_t)k0 * H_, H_, sn + G_ABUF, t);
        }
        asm volatile("cp.async.commit_group;" ::: "memory");
    }

    if (cslot < 4) {
        __half* dst = g_hb2 + (size_t)cslot * (B_ * S_ * H_);
        #pragma unroll
        for (int mt = 0; mt < 2; mt++)
            #pragma unroll
            for (int nv = 0; nv < 8; nv++) {
                const int row = m0 + wm * 32 + mt * 16 + (lane >> 2);
                const int col = o0 + wn * 64 + nv * 8 + (lane & 3) * 2;
                *reinterpret_cast<__half2*>(dst + (size_t)row * H_ + col) =
                    __floats2half2_rn(acc[mt][nv][0], acc[mt][nv][1]);
                *reinterpret_cast<__half2*>(dst + (size_t)(row + 8) * H_ + col) =
                    __floats2half2_rn(acc[mt][nv][2], acc[mt][nv][3]);
            }
    } else {
        #pragma unroll
        for (int mt = 0; mt < 2; mt++)
            #pragma unroll
            for (int nv = 0; nv < 8; nv++) {
                const int row = m0 + wm * 32 + mt * 16 + (lane >> 2);
                const int col = o0 + wn * 64 + nv * 8 + (lane & 3) * 2;
                float2 v0, v1;
                v0.x = acc[mt][nv][0]; v0.y = acc[mt][nv][1];
                v1.x = acc[mt][nv][2]; v1.y = acc[mt][nv][3];
                *reinterpret_cast<float2*>(out + (size_t)row * H_ + col) = v0;
                *reinterpret_cast<float2*>(out + (size_t)(row + 8) * H_ + col) = v1;
            }
    }
}

// ---------------------------------------------------------------------------
// GEMM-OUT split-K(4): out += W[:, kc*256:+256] @ g_hb2[kc] (dense, ld=768).
// grid (6, 16, 4) = 384 CTAs, 128 thr, CTA 64x128, NC=8, 3-stage, red2.
// ---------------------------------------------------------------------------
__global__ __launch_bounds__(128, 4) void gemm_out_kernel(float* __restrict__ out) {
    __shared__ __align__(128) char sm[3 * G_STG];
    const int n0 = blockIdx.x * 128;         // col in [0,768)
    const int row0 = blockIdx.y * 64;        // global row in [0,1024)
    const int kc = blockIdx.z;               // 0..3
    const int b = row0 >> 8;

    const __half* A  = g_W + (size_t)row0 * KW + kc * 256;
    const __half* Bm = g_hb2 + ((size_t)kc * (B_ * S_) + (size_t)b * S_) * H_ + n0;

    const int t = threadIdx.x, lane = t & 31, wid = t >> 5;
    const int wm = wid & 1, wn = wid >> 1;
    const uint32_t smb = s2u(sm);

    float acc[2][8][4] = {};
    const int NC = 8;
    #pragma unroll 1
    for (int p = 0; p < 2; p++) {
        const int k0 = p * 32;
        const uint32_t st = smb + (uint32_t)p * G_STG;
        ld_a32(A + k0, KW, st, t);
        ld_b32(Bm + (size_t)k0 * H_, H_, st + G_ABUF, t);
        asm volatile("cp.async.commit_group;" ::: "memory");
    }
    for (int c = 0; c < NC; c++) {
        asm volatile("cp.async.wait_group 1;" ::: "memory");
        __syncthreads();
        const uint32_t st = smb + (uint32_t)(c % 3) * G_STG;
        sub_t4(st, st + G_ABUF, acc, lane, wm, wn);
        sub_t4(st + 32, st + G_ABUF + 16 * G_BP, acc, lane, wm, wn);
        if (c + 2 < NC) {
            const int k0 = (c + 2) * 32;
            const uint32_t sn = smb + (uint32_t)((c + 2) % 3) * G_STG;
            ld_a32(A + k0, KW, sn, t);
            ld_b32(Bm + (size_t)k0 * H_, H_, sn + G_ABUF, t);
        }
        asm volatile("cp.async.commit_group;" ::: "memory");
    }

    // epilogue: vector fire-and-forget reductions onto the fp32 base.
    #pragma unroll
    for (int mt = 0; mt < 2; mt++)
        #pragma unroll
        for (int nv = 0; nv < 8; nv++) {
            const int row = row0 + wm * 32 + mt * 16 + (lane >> 2);
            const int col = n0 + wn * 64 + nv * 8 + (lane & 3) * 2;
            red2(out + (size_t)row * H_ + col,       acc[mt][nv][0], acc[mt][nv][1]);
            red2(out + (size_t)(row + 8) * H_ + col, acc[mt][nv][2], acc[mt][nv][3]);
        }
}

// ---------------------------------------------------------------------------
extern "C" void kernel_launch(void* const* d_in, const int* in_sizes, int n_in,
                              void* d_out, int out_size) {
    const float* hidden     = (const float*)d_in[0]; // [4,256,768]
    const int*   rels       = (const int*)  d_in[1]; // [4,256,256]
    const float* basic      = (const float*)d_in[2]; // [4,768,768]
    const float* rel_weight = (const float*)d_in[3]; // [64,4]
    const float* self_w     = (const float*)d_in[4]; // [768,768] (out,in)
    float* out = (float*)d_out;                      // [4,256,768]

    prep_kernel<<<NB_H + NB_BAS + NB_SELF + NB_RELS, 256>>>(hidden, basic, self_w, rels);
    build_w_kernel<<<B_ * S_, 256>>>(rels, rel_weight);
    gemm_hb_kernel<<<dim3(NTOT / 128, (B_ * S_) / 64), 128>>>(out);
    gemm_out_kernel<<<dim3(H_ / 128, (B_ * S_) / 64, 4), 128>>>(out);
}

// round 14
// speedup vs baseline: 1.0149x; 1.0054x over previous
#include <cuda_runtime.h>
#include <cuda_fp16.h>
#include <cstdint>

#define B_   4
#define S_   256
#define H_   768
#define NTOT 3840   // 5*768 : 4 basis slots + self slot
#define KW   1024   // 4*256 : step-2 K (4 c-blocks of 256)

// ---------------- static device scratch -------------------------------------
__device__ __align__(256) __half g_h[B_ * S_ * H_];      // hidden fp16 [1024][768]
__device__ __align__(256) __half g_bas[4 * H_ * H_];     // basic fp16 [c][h][o]
__device__ __align__(256) __half g_self[H_ * H_];        // selfw^T fp16 [h][o]
__device__ __align__(256) __half g_W[B_ * S_ * KW];      // W [b][i][c*256+j]
__device__ __align__(256) __half g_hb2[4 * B_ * S_ * H_];// hb slot-major [slot][1024][768]
__device__ __align__(256) int    g_relsT[B_ * S_ * S_];  // rels transposed

// ---------------- helpers ---------------------------------------------------
__device__ __forceinline__ uint32_t s2u(const void* p) {
    uint32_t a;
    asm("{ .reg .u64 t; cvta.to.shared.u64 t, %1; cvt.u32.u64 %0, t; }"
        : "=r"(a) : "l"(p));
    return a;
}
__device__ __forceinline__ void cp16(uint32_t dst, const void* src) {
    asm volatile("cp.async.cg.shared.global [%0], [%1], 16;"
                 :: "r"(dst), "l"(src) : "memory");
}
__device__ __forceinline__ void ldsm4(uint32_t* r, uint32_t addr) {
    asm volatile("ldmatrix.sync.aligned.m8n8.x4.shared.b16 {%0,%1,%2,%3}, [%4];"
                 : "=r"(r[0]), "=r"(r[1]), "=r"(r[2]), "=r"(r[3]) : "r"(addr));
}
__device__ __forceinline__ void ldsm4t(uint32_t* r, uint32_t addr) {
    asm volatile("ldmatrix.sync.aligned.m8n8.x4.trans.shared.b16 {%0,%1,%2,%3}, [%4];"
                 : "=r"(r[0]), "=r"(r[1]), "=r"(r[2]), "=r"(r[3]) : "r"(addr));
}
__device__ __forceinline__ void mma_f16(float* d, const uint32_t* a,
                                        uint32_t b0, uint32_t b1) {
    asm volatile("mma.sync.aligned.m16n8k16.row.col.f32.f16.f16.f32 "
                 "{%0,%1,%2,%3}, {%4,%5,%6,%7}, {%8,%9}, {%0,%1,%2,%3};"
                 : "+f"(d[0]), "+f"(d[1]), "+f"(d[2]), "+f"(d[3])
                 : "r"(a[0]), "r"(a[1]), "r"(a[2]), "r"(a[3]), "r"(b0), "r"(b1));
}
// fire-and-forget vector reduction (sm_90+)
__device__ __forceinline__ void red2(float* p, float x, float y) {
    asm volatile("red.global.add.v2.f32 [%0], {%1, %2};"
                 :: "l"(p), "f"(x), "f"(y) : "memory");
}

// ---------------- GEMM geometry ----------------------------------------------
// A: rows of 64B (32 halves, one 32-K chunk), pitch 80 -> conflict-free ldsm.
// B: 32 k-rows, pitch 272 (128n) / 144 (64n) -> conflict-free trans ldsm.
#define A_PITCH 80
#define HB_BP   272
#define HB_ABUF (64 * A_PITCH)               // 5120
#define HB_BBUF (32 * HB_BP)                 // 8704
#define HB_STG  (HB_ABUF + HB_BBUF)          // 13824
#define OUT_BP   144
#define OUT_BBUF (32 * OUT_BP)               // 4608
#define OUT_STG  (HB_ABUF + OUT_BBUF)        // 9728

__device__ __forceinline__ void ld_a32(const __half* __restrict__ src, int ld,
                                       uint32_t s, int t) {
    #pragma unroll
    for (int u = 0; u < 2; u++) {
        const int id = t + 128 * u;
        const int r = id >> 2, seg = id & 3;
        cp16(s + r * A_PITCH + seg * 16, src + (size_t)r * ld + seg * 8);
    }
}
template<int NCOLS, int BP>
__device__ __forceinline__ void ld_b32(const __half* __restrict__ src, int ld,
                                       uint32_t s, int t) {
    #pragma unroll
    for (int u = 0; u < 32 * (NCOLS / 8) / 128; u++) {
        const int id = t + 128 * u;
        const int k = id / (NCOLS / 8), q = id % (NCOLS / 8);
        cp16(s + k * BP + q * 16, src + (size_t)k * ld + q * 8);
    }
}

// One 16-K sub-chunk, trans-B. Warp tile 32 x (NG*16).
template<int BP, int NG>
__device__ __forceinline__ void sub_t(uint32_t a_s, uint32_t b_s,
                                      float acc[2][NG * 2][4],
                                      int lane, int wm, int wn)
{
    const int arow = wm * 32 + (lane & 15);
    const uint32_t abase = a_s + (uint32_t)arow * A_PITCH + (uint32_t)(lane >> 4) * 16;
    uint32_t ah[2][4], bh[NG][4];
    ldsm4(ah[0], abase);
    ldsm4(ah[1], abase + 16 * A_PITCH);
    const int krow = (lane & 7) | ((lane >> 1) & 8);
    const int noff = (lane & 8) ? 16 : 0;
    #pragma unroll
    for (int g = 0; g < NG; g++)
        ldsm4t(bh[g], b_s + (uint32_t)krow * BP + (uint32_t)(wn * (NG * 32) + g * 32) + noff);
    #pragma unroll
    for (int mt = 0; mt < 2; mt++)
        #pragma unroll
        for (int g = 0; g < NG; g++)
            #pragma unroll
            for (int s = 0; s < 2; s++)
                mma_f16(acc[mt][g * 2 + s], ah[mt], bh[g][s], bh[g][s + 2]);
}

// ---------------------------------------------------------------------------
// Fused prep: cvt hidden | cvt basic | transpose selfw | transpose rels.
// ---------------------------------------------------------------------------
#define NB_H    768
#define NB_BAS  2304
#define NB_SELF 576
#define NB_RELS 256

__global__ __launch_bounds__(256) void prep_kernel(
    const float* __restrict__ hidden, const float* __restrict__ basic,
    const float* __restrict__ selfw, const int* __restrict__ rels)
{
    const int blk = blockIdx.x;
    const int t = threadIdx.x;
    if (blk < NB_H + NB_BAS) {
        const float* src; __half* dst; int i;
        if (blk < NB_H) { src = hidden; dst = g_h; i = blk * 256 + t; }
        else            { src = basic;  dst = g_bas; i = (blk - NB_H) * 256 + t; }
        float4 v = reinterpret_cast<const float4*>(src)[i];
        reinterpret_cast<__half2*>(dst)[i * 2]     = __floats2half2_rn(v.x, v.y);
        reinterpret_cast<__half2*>(dst)[i * 2 + 1] = __floats2half2_rn(v.z, v.w);
    } else if (blk < NB_H + NB_BAS + NB_SELF) {
        __shared__ float tile[32][33];
        const int tl = blk - (NB_H + NB_BAS);
        const int h0 = (tl % 24) * 32, o0 = (tl / 24) * 32;
        const int tx = t & 31, ty = t >> 5;
        #pragma unroll
        for (int r = 0; r < 4; r++)
            tile[ty + 8 * r][tx] = selfw[(size_t)(o0 + ty + 8 * r) * H_ + h0 + tx];
        __syncthreads();
        #pragma unroll
        for (int r = 0; r < 4; r++)
            g_self[(size_t)(h0 + ty + 8 * r) * H_ + o0 + tx] =
                __float2half(tile[tx][ty + 8 * r]);
    } else {
        __shared__ int tile[32][33];
        const int id = blk - (NB_H + NB_BAS + NB_SELF);
        const int b = id >> 6, tl = id & 63;
        const int j0 = (tl & 7) * 32, i0 = (tl >> 3) * 32;
        const int tx = t & 31, ty = t >> 5;
        #pragma unroll
        for (int r = 0; r < 4; r++)
            tile[ty + 8 * r][tx] = rels[((size_t)b * S_ + i0 + ty + 8 * r) * S_ + j0 + tx];
        __syncthreads();
        #pragma unroll
        for (int r = 0; r < 4; r++)
            g_relsT[((size_t)b * S_ + j0 + ty + 8 * r) * S_ + i0 + tx] = tile[tx][ty + 8 * r];
    }
}

// ---------------------------------------------------------------------------
// build_w: histogram + W[b][i][c*256+j] fp16. All reads coalesced.
// ---------------------------------------------------------------------------
__global__ void build_w_kernel(const int* __restrict__ rels,
                               const float* __restrict__ rel_weight) {
    const int bi = blockIdx.x;
    const int b = bi >> 8;
    const int i = bi & 255;
    const int t = threadIdx.x;

    __shared__ int   cf[32], cr[32];
    __shared__ float inv_f[32], inv_r[32];
    __shared__ float rw[64 * 4];

    if (t < 32) { cf[t] = 0; cr[t] = 0; }
    rw[t] = rel_weight[t];
    __syncthreads();

    const int lf = rels[(b * S_ + i) * S_ + t];
    const int lr = g_relsT[(b * S_ + i) * S_ + t];
    if (lf > 0) atomicAdd(&cf[lf], 1);
    if (lr > 0) atomicAdd(&cr[lr], 1);
    __syncthreads();

    if (t < 32) {
        inv_f[t] = 1.0f / (float)(cf[t] > 0 ? cf[t] : 1);
        inv_r[t] = 1.0f / (float)(cr[t] > 0 ? cr[t] : 1);
    }
    __syncthreads();

    float w[4] = {0.f, 0.f, 0.f, 0.f};
    if (lf > 0) {
        const float s = inv_f[lf];
        #pragma unroll
        for (int c = 0; c < 4; c++) w[c] += rw[lf * 4 + c] * s;
    }
    if (lr > 0) {
        const float s = inv_r[lr];
        #pragma unroll
        for (int c = 0; c < 4; c++) w[c] += rw[(lr + 32) * 4 + c] * s;
    }
    #pragma unroll
    for (int c = 0; c < 4; c++)
        g_W[((size_t)(b * S_ + i)) * KW + c * 256 + t] = __float2half(w[c]);
}

// ---------------------------------------------------------------------------
// GEMM-HB: g_h (1024x768) @ [basic|selfT] (768x3840).
// grid (30, 16) = 480 CTAs, 128 thr, CTA 64x128, NC=24, 3-stage.
// cslot<4: write fp16 into slot-major g_hb2[cslot]. cslot==4: fp32 base of out.
// ---------------------------------------------------------------------------
__global__ __launch_bounds__(128, 4) void gemm_hb_kernel(float* __restrict__ out) {
    __shared__ __align__(128) char sm[3 * HB_STG];
    const int n0 = blockIdx.x * 128;     // never straddles a 768-slot
    const int m0 = blockIdx.y * 64;      // global row in [0,1024)
    const int cslot = n0 / 768;
    const int o0 = n0 - cslot * 768;

    const __half* A  = g_h + (size_t)m0 * H_;
    const __half* Bm = (cslot < 4) ? g_bas + (size_t)cslot * H_ * H_ + o0
                                   : g_self + o0;

    const int t = threadIdx.x, lane = t & 31, wid = t >> 5;
    const int wm = wid & 1, wn = wid >> 1;
    const uint32_t smb = s2u(sm);

    float acc[2][8][4] = {};
    const int NC = 24;
    #pragma unroll 1
    for (int p = 0; p < 2; p++) {
        const int k0 = p * 32;
        const uint32_t st = smb + (uint32_t)p * HB_STG;
        ld_a32(A + k0, H_, st, t);
        ld_b32<128, HB_BP>(Bm + (size_t)k0 * H_, H_, st + HB_ABUF, t);
        asm volatile("cp.async.commit_group;" ::: "memory");
    }
    for (int c = 0; c < NC; c++) {
        asm volatile("cp.async.wait_group 1;" ::: "memory");
        __syncthreads();
        const uint32_t st = smb + (uint32_t)(c % 3) * HB_STG;
        sub_t<HB_BP, 4>(st, st + HB_ABUF, acc, lane, wm, wn);
        sub_t<HB_BP, 4>(st + 32, st + HB_ABUF + 16 * HB_BP, acc, lane, wm, wn);
        if (c + 2 < NC) {
            const int k0 = (c + 2) * 32;
            const uint32_t sn = smb + (uint32_t)((c + 2) % 3) * HB_STG;
            ld_a32(A + k0, H_, sn, t);
            ld_b32<128, HB_BP>(Bm + (size_t)k0 * H_, H_, sn + HB_ABUF, t);
        }
        asm volatile("cp.async.commit_group;" ::: "memory");
    }

    if (cslot < 4) {
        __half* dst = g_hb2 + (size_t)cslot * (B_ * S_ * H_);
        #pragma unroll
        for (int mt = 0; mt < 2; mt++)
            #pragma unroll
            for (int nv = 0; nv < 8; nv++) {
                const int row = m0 + wm * 32 + mt * 16 + (lane >> 2);
                const int col = o0 + wn * 64 + nv * 8 + (lane & 3) * 2;
                *reinterpret_cast<__half2*>(dst + (size_t)row * H_ + col) =
                    __floats2half2_rn(acc[mt][nv][0], acc[mt][nv][1]);
                *reinterpret_cast<__half2*>(dst + (size_t)(row + 8) * H_ + col) =
                    __floats2half2_rn(acc[mt][nv][2], acc[mt][nv][3]);
            }
    } else {
        #pragma unroll
        for (int mt = 0; mt < 2; mt++)
            #pragma unroll
            for (int nv = 0; nv < 8; nv++) {
                const int row = m0 + wm * 32 + mt * 16 + (lane >> 2);
                const int col = o0 + wn * 64 + nv * 8 + (lane & 3) * 2;
                float2 v0, v1;
                v0.x = acc[mt][nv][0]; v0.y = acc[mt][nv][1];
                v1.x = acc[mt][nv][2]; v1.y = acc[mt][nv][3];
                *reinterpret_cast<float2*>(out + (size_t)row * H_ + col) = v0;
                *reinterpret_cast<float2*>(out + (size_t)(row + 8) * H_ + col) = v1;
            }
    }
}

// ---------------------------------------------------------------------------
// GEMM-OUT split-K(2): out += W[:, kc*512:+512] @ hb slots {2kc, 2kc+1}.
// grid (12, 16, 2) = 384 CTAs, 128 thr, CTA 64x64, warp 32x32, NC=16,
// 3-stage, 6 CTAs/SM, red2 epilogue.
// ---------------------------------------------------------------------------
__global__ __launch_bounds__(128, 6) void gemm_out_kernel(float* __restrict__ out) {
    __shared__ __align__(128) char sm[3 * OUT_STG];
    const int n0 = blockIdx.x * 64;          // col in [0,768)
    const int row0 = blockIdx.y * 64;        // global row in [0,1024)
    const int kc = blockIdx.z;               // 0..1
    const int b = row0 >> 8;

    const __half* A = g_W + (size_t)row0 * KW + kc * 512;
    // B chunk at global k: slot = kc*2 + (k>>8), row = k&255 (32-chunks never straddle)
    const __half* Bbase = g_hb2 + (size_t)(kc * 2) * (B_ * S_ * H_)
                        + (size_t)b * S_ * H_ + n0;

    const int t = threadIdx.x, lane = t & 31, wid = t >> 5;
    const int wm = wid & 1, wn = wid >> 1;
    const uint32_t smb = s2u(sm);

    float acc[2][4][4] = {};
    const int NC = 16;
    #pragma unroll 1
    for (int p = 0; p < 2; p++) {
        const int k0 = p * 32;
        const size_t boff = (size_t)(k0 >> 8) * (B_ * S_ * H_) + (size_t)(k0 & 255) * H_;
        const uint32_t st = smb + (uint32_t)p * OUT_STG;
        ld_a32(A + k0, KW, st, t);
        ld_b32<64, OUT_BP>(Bbase + boff, H_, st + HB_ABUF, t);
        asm volatile("cp.async.commit_group;" ::: "memory");
    }
    for (int c = 0; c < NC; c++) {
        asm volatile("cp.async.wait_group 1;" ::: "memory");
        __syncthreads();
        const uint32_t st = smb + (uint32_t)(c % 3) * OUT_STG;
        sub_t<OUT_BP, 2>(st, st + HB_ABUF, acc, lane, wm, wn);
        sub_t<OUT_BP, 2>(st + 32, st + HB_ABUF + 16 * OUT_BP, acc, lane, wm, wn);
        if (c + 2 < NC) {
            const int k0 = (c + 2) * 32;
            const size_t boff = (size_t)(k0 >> 8) * (B_ * S_ * H_) + (size_t)(k0 & 255) * H_;
            const uint32_t sn = smb + (uint32_t)((c + 2) % 3) * OUT_STG;
            ld_a32(A + k0, KW, sn, t);
            ld_b32<64, OUT_BP>(Bbase + boff, H_, sn + HB_ABUF, t);
        }
        asm volatile("cp.async.commit_group;" ::: "memory");
    }

    // epilogue: vector fire-and-forget reductions onto the fp32 base.
    #pragma unroll
    for (int mt = 0; mt < 2; mt++)
        #pragma unroll
        for (int nv = 0; nv < 4; nv++) {
            const int row = row0 + wm * 32 + mt * 16 + (lane >> 2);
            const int col = n0 + wn * 32 + nv * 8 + (lane & 3) * 2;
            red2(out + (size_t)row * H_ + col,       acc[mt][nv][0], acc[mt][nv][1]);
            red2(out + (size_t)(row + 8) * H_ + col, acc[mt][nv][2], acc[mt][nv][3]);
        }
}

// ---------------------------------------------------------------------------
extern "C" void kernel_launch(void* const* d_in, const int* in_sizes, int n_in,
                              void* d_out, int out_size) {
    const float* hidden     = (const float*)d_in[0]; // [4,256,768]
    const int*   rels       = (const int*)  d_in[1]; // [4,256,256]
    const float* basic      = (const float*)d_in[2]; // [4,768,768]
    const float* rel_weight = (const float*)d_in[3]; // [64,4]
    const float* self_w     = (const float*)d_in[4]; // [768,768] (out,in)
    float* out = (float*)d_out;                      // [4,256,768]

    prep_kernel<<<NB_H + NB_BAS + NB_SELF + NB_RELS, 256>>>(hidden, basic, self_w, rels);
    build_w_kernel<<<B_ * S_, 256>>>(rels, rel_weight);
    gemm_hb_kernel<<<dim3(NTOT / 128, (B_ * S_) / 64), 128>>>(out);
    gemm_out_kernel<<<dim3(H_ / 64, (B_ * S_) / 64, 2), 128>>>(out);
}

// round 15
// speedup vs baseline: 1.0563x; 1.0408x over previous
#include <cuda_runtime.h>
#include <cuda_fp16.h>
#include <cstdint>

#define B_   4
#define S_   256
#define H_   768
#define NTOT 3840   // 5*768 : 4 basis slots + self slot
#define KW   1024   // 4*256 : step-2 K (4 c-blocks of 256)

// ---------------- static device scratch -------------------------------------
__device__ __align__(256) __half g_h[B_ * S_ * H_];      // hidden fp16 [1024][768]
__device__ __align__(256) __half g_bas[4 * H_ * H_];     // basic fp16 [c][h][o]
__device__ __align__(256) __half g_self[H_ * H_];        // selfw^T fp16 [h][o]
__device__ __align__(256) __half g_W[B_ * S_ * KW];      // W [b][i][c*256+j]
__device__ __align__(256) __half g_hb2[4 * B_ * S_ * H_];// hb slot-major [slot][1024][768]
__device__ __align__(256) int    g_relsT[B_ * S_ * S_];  // rels transposed

// ---------------- helpers ---------------------------------------------------
__device__ __forceinline__ uint32_t s2u(const void* p) {
    uint32_t a;
    asm("{ .reg .u64 t; cvta.to.shared.u64 t, %1; cvt.u32.u64 %0, t; }"
        : "=r"(a) : "l"(p));
    return a;
}
__device__ __forceinline__ void cp16(uint32_t dst, const void* src) {
    asm volatile("cp.async.cg.shared.global [%0], [%1], 16;"
                 :: "r"(dst), "l"(src) : "memory");
}
__device__ __forceinline__ void ldsm4(uint32_t* r, uint32_t addr) {
    asm volatile("ldmatrix.sync.aligned.m8n8.x4.shared.b16 {%0,%1,%2,%3}, [%4];"
                 : "=r"(r[0]), "=r"(r[1]), "=r"(r[2]), "=r"(r[3]) : "r"(addr));
}
__device__ __forceinline__ void ldsm4t(uint32_t* r, uint32_t addr) {
    asm volatile("ldmatrix.sync.aligned.m8n8.x4.trans.shared.b16 {%0,%1,%2,%3}, [%4];"
                 : "=r"(r[0]), "=r"(r[1]), "=r"(r[2]), "=r"(r[3]) : "r"(addr));
}
__device__ __forceinline__ void mma_f16(float* d, const uint32_t* a,
                                        uint32_t b0, uint32_t b1) {
    asm volatile("mma.sync.aligned.m16n8k16.row.col.f32.f16.f16.f32 "
                 "{%0,%1,%2,%3}, {%4,%5,%6,%7}, {%8,%9}, {%0,%1,%2,%3};"
                 : "+f"(d[0]), "+f"(d[1]), "+f"(d[2]), "+f"(d[3])
                 : "r"(a[0]), "r"(a[1]), "r"(a[2]), "r"(a[3]), "r"(b0), "r"(b1));
}
// fire-and-forget vector reduction (sm_90+)
__device__ __forceinline__ void red2(float* p, float x, float y) {
    asm volatile("red.global.add.v2.f32 [%0], {%1, %2};"
                 :: "l"(p), "f"(x), "f"(y) : "memory");
}

// ---------------- GEMM geometry ----------------------------------------------
#define A_PITCH 80
#define HB_BP   272
#define HB_ABUF (64 * A_PITCH)               // 5120
#define HB_BBUF (32 * HB_BP)                 // 8704
#define HB_STG  (HB_ABUF + HB_BBUF)          // 13824
#define OUT_BP   144
#define OUT_BBUF (32 * OUT_BP)               // 4608
#define OUT_STG  (HB_ABUF + OUT_BBUF)        // 9728

__device__ __forceinline__ void ld_a32(const __half* __restrict__ src, int ld,
                                       uint32_t s, int t) {
    #pragma unroll
    for (int u = 0; u < 2; u++) {
        const int id = t + 128 * u;
        const int r = id >> 2, seg = id & 3;
        cp16(s + r * A_PITCH + seg * 16, src + (size_t)r * ld + seg * 8);
    }
}
template<int NCOLS, int BP>
__device__ __forceinline__ void ld_b32(const __half* __restrict__ src, int ld,
                                       uint32_t s, int t) {
    #pragma unroll
    for (int u = 0; u < 32 * (NCOLS / 8) / 128; u++) {
        const int id = t + 128 * u;
        const int k = id / (NCOLS / 8), q = id % (NCOLS / 8);
        cp16(s + k * BP + q * 16, src + (size_t)k * ld + q * 8);
    }
}

// One 16-K sub-chunk, trans-B. Warp tile 32 x (NG*16).
template<int BP, int NG>
__device__ __forceinline__ void sub_t(uint32_t a_s, uint32_t b_s,
                                      float acc[2][NG * 2][4],
                                      int lane, int wm, int wn)
{
    const int arow = wm * 32 + (lane & 15);
    const uint32_t abase = a_s + (uint32_t)arow * A_PITCH + (uint32_t)(lane >> 4) * 16;
    uint32_t ah[2][4], bh[NG][4];
    ldsm4(ah[0], abase);
    ldsm4(ah[1], abase + 16 * A_PITCH);
    const int krow = (lane & 7) | ((lane >> 1) & 8);
    const int noff = (lane & 8) ? 16 : 0;
    #pragma unroll
    for (int g = 0; g < NG; g++)
        ldsm4t(bh[g], b_s + (uint32_t)krow * BP + (uint32_t)(wn * (NG * 32) + g * 32) + noff);
    #pragma unroll
    for (int mt = 0; mt < 2; mt++)
        #pragma unroll
        for (int g = 0; g < NG; g++)
            #pragma unroll
            for (int s = 0; s < 2; s++)
                mma_f16(acc[mt][g * 2 + s], ah[mt], bh[g][s], bh[g][s + 2]);
}

// ---------------------------------------------------------------------------
// Fused prep: cvt hidden | cvt basic | transpose selfw | transpose rels.
// ---------------------------------------------------------------------------
#define NB_H    768
#define NB_BAS  2304
#define NB_SELF 576
#define NB_RELS 256

__global__ __launch_bounds__(256) void prep_kernel(
    const float* __restrict__ hidden, const float* __restrict__ basic,
    const float* __restrict__ selfw, const int* __restrict__ rels)
{
    const int blk = blockIdx.x;
    const int t = threadIdx.x;
    if (blk < NB_H + NB_BAS) {
        const float* src; __half* dst; int i;
        if (blk < NB_H) { src = hidden; dst = g_h; i = blk * 256 + t; }
        else            { src = basic;  dst = g_bas; i = (blk - NB_H) * 256 + t; }
        float4 v = reinterpret_cast<const float4*>(src)[i];
        reinterpret_cast<__half2*>(dst)[i * 2]     = __floats2half2_rn(v.x, v.y);
        reinterpret_cast<__half2*>(dst)[i * 2 + 1] = __floats2half2_rn(v.z, v.w);
    } else if (blk < NB_H + NB_BAS + NB_SELF) {
        __shared__ float tile[32][33];
        const int tl = blk - (NB_H + NB_BAS);
        const int h0 = (tl % 24) * 32, o0 = (tl / 24) * 32;
        const int tx = t & 31, ty = t >> 5;
        #pragma unroll
        for (int r = 0; r < 4; r++)
            tile[ty + 8 * r][tx] = selfw[(size_t)(o0 + ty + 8 * r) * H_ + h0 + tx];
        __syncthreads();
        #pragma unroll
        for (int r = 0; r < 4; r++)
            g_self[(size_t)(h0 + ty + 8 * r) * H_ + o0 + tx] =
                __float2half(tile[tx][ty + 8 * r]);
    } else {
        __shared__ int tile[32][33];
        const int id = blk - (NB_H + NB_BAS + NB_SELF);
        const int b = id >> 6, tl = id & 63;
        const int j0 = (tl & 7) * 32, i0 = (tl >> 3) * 32;
        const int tx = t & 31, ty = t >> 5;
        #pragma unroll
        for (int r = 0; r < 4; r++)
            tile[ty + 8 * r][tx] = rels[((size_t)b * S_ + i0 + ty + 8 * r) * S_ + j0 + tx];
        __syncthreads();
        #pragma unroll
        for (int r = 0; r < 4; r++)
            g_relsT[((size_t)b * S_ + j0 + ty + 8 * r) * S_ + i0 + tx] = tile[tx][ty + 8 * r];
    }
}

// ---------------------------------------------------------------------------
// FUSED GEMM-HB + build_w. Grid = 480 hb blocks + 1024 build_w blocks,
// 128 threads each.
//  hb part: g_h (1024x768) @ [basic|selfT] (768x3840), CTA 64x128, NC=24,
//           3-stage. cslot<4 -> fp16 slot-major g_hb2; cslot==4 -> fp32 out.
//  build_w part: per (b,i) histogram + W[b][i][c*256+j] fp16 (128 thr, 2 j's).
// ---------------------------------------------------------------------------
#define HB_NBLK 480

__global__ __launch_bounds__(128, 4) void fused_hb_kernel(
    float* __restrict__ out,
    const int* __restrict__ rels, const float* __restrict__ rel_weight)
{
    __shared__ __align__(128) char sm[3 * HB_STG];
    const int bx = blockIdx.x;
    const int t = threadIdx.x;

    if (bx >= HB_NBLK) {
        // ---------------- build_w partition ----------------
        const int id = bx - HB_NBLK;
        const int b = id >> 8;
        const int i = id & 255;

        int*   cf    = reinterpret_cast<int*>(sm);          // 32
        int*   cr    = cf + 32;                             // 32
        float* inv_f = reinterpret_cast<float*>(cr + 32);   // 32
        float* inv_r = inv_f + 32;                          // 32
        float* rw    = inv_r + 32;                          // 256

        if (t < 32) { cf[t] = 0; cr[t] = 0; }
        rw[t] = rel_weight[t];
        rw[t + 128] = rel_weight[t + 128];
        __syncthreads();

        int lf[2], lr[2];
        #pragma unroll
        for (int u = 0; u < 2; u++) {
            const int j = t + 128 * u;
            lf[u] = rels[(b * S_ + i) * S_ + j];
            lr[u] = g_relsT[(b * S_ + i) * S_ + j];
            if (lf[u] > 0) atomicAdd(&cf[lf[u]], 1);
            if (lr[u] > 0) atomicAdd(&cr[lr[u]], 1);
        }
        __syncthreads();

        if (t < 32) {
            inv_f[t] = 1.0f / (float)(cf[t] > 0 ? cf[t] : 1);
            inv_r[t] = 1.0f / (float)(cr[t] > 0 ? cr[t] : 1);
        }
        __syncthreads();

        #pragma unroll
        for (int u = 0; u < 2; u++) {
            const int j = t + 128 * u;
            float w[4] = {0.f, 0.f, 0.f, 0.f};
            if (lf[u] > 0) {
                const float s = inv_f[lf[u]];
                #pragma unroll
                for (int c = 0; c < 4; c++) w[c] += rw[lf[u] * 4 + c] * s;
            }
            if (lr[u] > 0) {
                const float s = inv_r[lr[u]];
                #pragma unroll
                for (int c = 0; c < 4; c++) w[c] += rw[(lr[u] + 32) * 4 + c] * s;
            }
            #pragma unroll
            for (int c = 0; c < 4; c++)
                g_W[((size_t)(b * S_ + i)) * KW + c * 256 + j] = __float2half(w[c]);
        }
        return;
    }

    // ---------------- hb GEMM partition ----------------
    const int n0 = (bx % 30) * 128;      // never straddles a 768-slot
    const int m0 = (bx / 30) * 64;       // global row in [0,1024)
    const int cslot = n0 / 768;
    const int o0 = n0 - cslot * 768;

    const __half* A  = g_h + (size_t)m0 * H_;
    const __half* Bm = (cslot < 4) ? g_bas + (size_t)cslot * H_ * H_ + o0
                                   : g_self + o0;

    const int lane = t & 31, wid = t >> 5;
    const int wm = wid & 1, wn = wid >> 1;
    const uint32_t smb = s2u(sm);

    float acc[2][8][4] = {};
    const int NC = 24;
    #pragma unroll 1
    for (int p = 0; p < 2; p++) {
        const int k0 = p * 32;
        const uint32_t st = smb + (uint32_t)p * HB_STG;
        ld_a32(A + k0, H_, st, t);
        ld_b32<128, HB_BP>(Bm + (size_t)k0 * H_, H_, st + HB_ABUF, t);
        asm volatile("cp.async.commit_group;" ::: "memory");
    }
    for (int c = 0; c < NC; c++) {
        asm volatile("cp.async.wait_group 1;" ::: "memory");
        __syncthreads();
        const uint32_t st = smb + (uint32_t)(c % 3) * HB_STG;
        sub_t<HB_BP, 4>(st, st + HB_ABUF, acc, lane, wm, wn);
        sub_t<HB_BP, 4>(st + 32, st + HB_ABUF + 16 * HB_BP, acc, lane, wm, wn);
        if (c + 2 < NC) {
            const int k0 = (c + 2) * 32;
            const uint32_t sn = smb + (uint32_t)((c + 2) % 3) * HB_STG;
            ld_a32(A + k0, H_, sn, t);
            ld_b32<128, HB_BP>(Bm + (size_t)k0 * H_, H_, sn + HB_ABUF, t);
        }
        asm volatile("cp.async.commit_group;" ::: "memory");
    }

    if (cslot < 4) {
        __half* dst = g_hb2 + (size_t)cslot * (B_ * S_ * H_);
        #pragma unroll
        for (int mt = 0; mt < 2; mt++)
            #pragma unroll
            for (int nv = 0; nv < 8; nv++) {
                const int row = m0 + wm * 32 + mt * 16 + (lane >> 2);
                const int col = o0 + wn * 64 + nv * 8 + (lane & 3) * 2;
                *reinterpret_cast<__half2*>(dst + (size_t)row * H_ + col) =
                    __floats2half2_rn(acc[mt][nv][0], acc[mt][nv][1]);
                *reinterpret_cast<__half2*>(dst + (size_t)(row + 8) * H_ + col) =
                    __floats2half2_rn(acc[mt][nv][2], acc[mt][nv][3]);
            }
    } else {
        #pragma unroll
        for (int mt = 0; mt < 2; mt++)
            #pragma unroll
            for (int nv = 0; nv < 8; nv++) {
                const int row = m0 + wm * 32 + mt * 16 + (lane >> 2);
                const int col = o0 + wn * 64 + nv * 8 + (lane & 3) * 2;
                float2 v0, v1;
                v0.x = acc[mt][nv][0]; v0.y = acc[mt][nv][1];
                v1.x = acc[mt][nv][2]; v1.y = acc[mt][nv][3];
                *reinterpret_cast<float2*>(out + (size_t)row * H_ + col) = v0;
                *reinterpret_cast<float2*>(out + (size_t)(row + 8) * H_ + col) = v1;
            }
    }
}

// ---------------------------------------------------------------------------
// GEMM-OUT split-K(2): out += W[:, kc*512:+512] @ hb slots {2kc, 2kc+1}.
// grid (12, 16, 2) = 384 CTAs, 128 thr, CTA 64x64, NC=16, 3-stage, red2.
// ---------------------------------------------------------------------------
__global__ __launch_bounds__(128, 6) void gemm_out_kernel(float* __restrict__ out) {
    __shared__ __align__(128) char sm[3 * OUT_STG];
    const int n0 = blockIdx.x * 64;          // col in [0,768)
    const int row0 = blockIdx.y * 64;        // global row in [0,1024)
    const int kc = blockIdx.z;               // 0..1
    const int b = row0 >> 8;

    const __half* A = g_W + (size_t)row0 * KW + kc * 512;
    const __half* Bbase = g_hb2 + (size_t)(kc * 2) * (B_ * S_ * H_)
                        + (size_t)b * S_ * H_ + n0;

    const int t = threadIdx.x, lane = t & 31, wid = t >> 5;
    const int wm = wid & 1, wn = wid >> 1;
    const uint32_t smb = s2u(sm);

    float acc[2][4][4] = {};
    const int NC = 16;
    #pragma unroll 1
    for (int p = 0; p < 2; p++) {
        const int k0 = p * 32;
        const size_t boff = (size_t)(k0 >> 8) * (B_ * S_ * H_) + (size_t)(k0 & 255) * H_;
        const uint32_t st = smb + (uint32_t)p * OUT_STG;
        ld_a32(A + k0, KW, st, t);
        ld_b32<64, OUT_BP>(Bbase + boff, H_, st + HB_ABUF, t);
        asm volatile("cp.async.commit_group;" ::: "memory");
    }
    for (int c = 0; c < NC; c++) {
        asm volatile("cp.async.wait_group 1;" ::: "memory");
        __syncthreads();
        const uint32_t st = smb + (uint32_t)(c % 3) * OUT_STG;
        sub_t<OUT_BP, 2>(st, st + HB_ABUF, acc, lane, wm, wn);
        sub_t<OUT_BP, 2>(st + 32, st + HB_ABUF + 16 * OUT_BP, acc, lane, wm, wn);
        if (c + 2 < NC) {
            const int k0 = (c + 2) * 32;
            const size_t boff = (size_t)(k0 >> 8) * (B_ * S_ * H_) + (size_t)(k0 & 255) * H_;
            const uint32_t sn = smb + (uint32_t)((c + 2) % 3) * OUT_STG;
            ld_a32(A + k0, KW, sn, t);
            ld_b32<64, OUT_BP>(Bbase + boff, H_, sn + HB_ABUF, t);
        }
        asm volatile("cp.async.commit_group;" ::: "memory");
    }

    #pragma unroll
    for (int mt = 0; mt < 2; mt++)
        #pragma unroll
        for (int nv = 0; nv < 4; nv++) {
            const int row = row0 + wm * 32 + mt * 16 + (lane >> 2);
            const int col = n0 + wn * 32 + nv * 8 + (lane & 3) * 2;
            red2(out + (size_t)row * H_ + col,       acc[mt][nv][0], acc[mt][nv][1]);
            red2(out + (size_t)(row + 8) * H_ + col, acc[mt][nv][2], acc[mt][nv][3]);
        }
}

// ---------------------------------------------------------------------------
extern "C" void kernel_launch(void* const* d_in, const int* in_sizes, int n_in,
                              void* d_out, int out_size) {
    const float* hidden     = (const float*)d_in[0]; // [4,256,768]
    const int*   rels       = (const int*)  d_in[1]; // [4,256,256]
    const float* basic      = (const float*)d_in[2]; // [4,768,768]
    const float* rel_weight = (const float*)d_in[3]; // [64,4]
    const float* self_w     = (const float*)d_in[4]; // [768,768] (out,in)
    float* out = (float*)d_out;                      // [4,256,768]

    prep_kernel<<<NB_H + NB_BAS + NB_SELF + NB_RELS, 256>>>(hidden, basic, self_w, rels);
    fused_hb_kernel<<<HB_NBLK + B_ * S_, 128>>>(out, rels, rel_weight);
    gemm_out_kernel<<<dim3(H_ / 64, (B_ * S_) / 64, 2), 128>>>(out);
}

// round 16
// speedup vs baseline: 1.0790x; 1.0216x over previous
#include <cuda_runtime.h>
#include <cuda_fp16.h>
#include <cstdint>

#define B_   4
#define S_   256
#define H_   768
#define NTOT 3840   // 5*768 : 4 basis slots + self slot
#define KW   1024   // 4*256 : step-2 K (4 c-blocks of 256)

// ---------------- static device scratch -------------------------------------
__device__ __align__(256) __half g_h[B_ * S_ * H_];      // hidden fp16 [1024][768]
__device__ __align__(256) __half g_bas[4 * H_ * H_];     // basic fp16 [c][h][o]
__device__ __align__(256) __half g_self[H_ * H_];        // selfw^T fp16 [h][o]
__device__ __align__(256) __half g_W[B_ * S_ * KW];      // W [b][i][c*256+j]
__device__ __align__(256) __half g_hb2[4 * B_ * S_ * H_];// hb slot-major [slot][1024][768]
__device__ __align__(256) int    g_relsT[B_ * S_ * S_];  // rels transposed

// ---------------- helpers ---------------------------------------------------
__device__ __forceinline__ uint32_t s2u(const void* p) {
    uint32_t a;
    asm("{ .reg .u64 t; cvta.to.shared.u64 t, %1; cvt.u32.u64 %0, t; }"
        : "=r"(a) : "l"(p));
    return a;
}
__device__ __forceinline__ void cp16(uint32_t dst, const void* src) {
    asm volatile("cp.async.cg.shared.global [%0], [%1], 16;"
                 :: "r"(dst), "l"(src) : "memory");
}
__device__ __forceinline__ void ldsm4(uint32_t* r, uint32_t addr) {
    asm volatile("ldmatrix.sync.aligned.m8n8.x4.shared.b16 {%0,%1,%2,%3}, [%4];"
                 : "=r"(r[0]), "=r"(r[1]), "=r"(r[2]), "=r"(r[3]) : "r"(addr));
}
__device__ __forceinline__ void ldsm4t(uint32_t* r, uint32_t addr) {
    asm volatile("ldmatrix.sync.aligned.m8n8.x4.trans.shared.b16 {%0,%1,%2,%3}, [%4];"
                 : "=r"(r[0]), "=r"(r[1]), "=r"(r[2]), "=r"(r[3]) : "r"(addr));
}
__device__ __forceinline__ void mma_f16(float* d, const uint32_t* a,
                                        uint32_t b0, uint32_t b1) {
    asm volatile("mma.sync.aligned.m16n8k16.row.col.f32.f16.f16.f32 "
                 "{%0,%1,%2,%3}, {%4,%5,%6,%7}, {%8,%9}, {%0,%1,%2,%3};"
                 : "+f"(d[0]), "+f"(d[1]), "+f"(d[2]), "+f"(d[3])
                 : "r"(a[0]), "r"(a[1]), "r"(a[2]), "r"(a[3]), "r"(b0), "r"(b1));
}
// fire-and-forget vector reduction (sm_90+)
__device__ __forceinline__ void red2(float* p, float x, float y) {
    asm volatile("red.global.add.v2.f32 [%0], {%1, %2};"
                 :: "l"(p), "f"(x), "f"(y) : "memory");
}

// ---------------- GEMM geometry ----------------------------------------------
#define A_PITCH 80
#define HB_BP   272
#define HB_ABUF (64 * A_PITCH)               // 5120
#define HB_BBUF (32 * HB_BP)                 // 8704
#define HB_STG  (HB_ABUF + HB_BBUF)          // 13824
#define OUT_BP   144
#define OUT_BBUF (32 * OUT_BP)               // 4608
#define OUT_STG  (HB_ABUF + OUT_BBUF)        // 9728

__device__ __forceinline__ void ld_a32(const __half* __restrict__ src, int ld,
                                       uint32_t s, int t) {
    #pragma unroll
    for (int u = 0; u < 2; u++) {
        const int id = t + 128 * u;
        const int r = id >> 2, seg = id & 3;
        cp16(s + r * A_PITCH + seg * 16, src + (size_t)r * ld + seg * 8);
    }
}
template<int NCOLS, int BP>
__device__ __forceinline__ void ld_b32(const __half* __restrict__ src, int ld,
                                       uint32_t s, int t) {
    #pragma unroll
    for (int u = 0; u < 32 * (NCOLS / 8) / 128; u++) {
        const int id = t + 128 * u;
        const int k = id / (NCOLS / 8), q = id % (NCOLS / 8);
        cp16(s + k * BP + q * 16, src + (size_t)k * ld + q * 8);
    }
}

// One 16-K sub-chunk, trans-B. Warp tile 32 x (NG*16).
template<int BP, int NG>
__device__ __forceinline__ void sub_t(uint32_t a_s, uint32_t b_s,
                                      float acc[2][NG * 2][4],
                                      int lane, int wm, int wn)
{
    const int arow = wm * 32 + (lane & 15);
    const uint32_t abase = a_s + (uint32_t)arow * A_PITCH + (uint32_t)(lane >> 4) * 16;
    uint32_t ah[2][4], bh[NG][4];
    ldsm4(ah[0], abase);
    ldsm4(ah[1], abase + 16 * A_PITCH);
    const int krow = (lane & 7) | ((lane >> 1) & 8);
    const int noff = (lane & 8) ? 16 : 0;
    #pragma unroll
    for (int g = 0; g < NG; g++)
        ldsm4t(bh[g], b_s + (uint32_t)krow * BP + (uint32_t)(wn * (NG * 32) + g * 32) + noff);
    #pragma unroll
    for (int mt = 0; mt < 2; mt++)
        #pragma unroll
        for (int g = 0; g < NG; g++)
            #pragma unroll
            for (int s = 0; s < 2; s++)
                mma_f16(acc[mt][g * 2 + s], ah[mt], bh[g][s], bh[g][s + 2]);
}

// ---------------------------------------------------------------------------
// Fused prep: cvt hidden | cvt basic | cvt selfw->transpose | transpose rels.
// Convert partitions: 2 float4 per thread (MLP=2).
// ---------------------------------------------------------------------------
#define NB_H    384     // 786432 floats / (256 thr * 8)
#define NB_BAS  1152    // 2359296 / 2048
#define NB_SELF 576     // 24x24 32x32-tiles (transpose)
#define NB_RELS 256     // 4 * 64 tiles

__global__ __launch_bounds__(256) void prep_kernel(
    const float* __restrict__ hidden, const float* __restrict__ basic,
    const float* __restrict__ selfw, const int* __restrict__ rels)
{
    const int blk = blockIdx.x;
    const int t = threadIdx.x;
    if (blk < NB_H + NB_BAS) {
        const float* src; __half* dst; int base;
        if (blk < NB_H) { src = hidden; dst = g_h; base = blk * 512; }
        else            { src = basic;  dst = g_bas; base = (blk - NB_H) * 512; }
        const int i0 = base + t;
        const int i1 = base + t + 256;
        float4 v0 = reinterpret_cast<const float4*>(src)[i0];
        float4 v1 = reinterpret_cast<const float4*>(src)[i1];
        __half2 a0 = __floats2half2_rn(v0.x, v0.y);
        __half2 b0 = __floats2half2_rn(v0.z, v0.w);
        __half2 a1 = __floats2half2_rn(v1.x, v1.y);
        __half2 b1 = __floats2half2_rn(v1.z, v1.w);
        uint2 p0, p1;
        p0.x = *reinterpret_cast<uint32_t*>(&a0); p0.y = *reinterpret_cast<uint32_t*>(&b0);
        p1.x = *reinterpret_cast<uint32_t*>(&a1); p1.y = *reinterpret_cast<uint32_t*>(&b1);
        reinterpret_cast<uint2*>(dst)[i0] = p0;
        reinterpret_cast<uint2*>(dst)[i1] = p1;
    } else if (blk < NB_H + NB_BAS + NB_SELF) {
        __shared__ float tile[32][33];
        const int tl = blk - (NB_H + NB_BAS);
        const int h0 = (tl % 24) * 32, o0 = (tl / 24) * 32;
        const int tx = t & 31, ty = t >> 5;
        #pragma unroll
        for (int r = 0; r < 4; r++)
            tile[ty + 8 * r][tx] = selfw[(size_t)(o0 + ty + 8 * r) * H_ + h0 + tx];
        __syncthreads();
        #pragma unroll
        for (int r = 0; r < 4; r++)
            g_self[(size_t)(h0 + ty + 8 * r) * H_ + o0 + tx] =
                __float2half(tile[tx][ty + 8 * r]);
    } else {
        __shared__ int tile[32][33];
        const int id = blk - (NB_H + NB_BAS + NB_SELF);
        const int b = id >> 6, tl = id & 63;
        const int j0 = (tl & 7) * 32, i0 = (tl >> 3) * 32;
        const int tx = t & 31, ty = t >> 5;
        #pragma unroll
        for (int r = 0; r < 4; r++)
            tile[ty + 8 * r][tx] = rels[((size_t)b * S_ + i0 + ty + 8 * r) * S_ + j0 + tx];
        __syncthreads();
        #pragma unroll
        for (int r = 0; r < 4; r++)
            g_relsT[((size_t)b * S_ + j0 + ty + 8 * r) * S_ + i0 + tx] = tile[tx][ty + 8 * r];
    }
}

// ---------------------------------------------------------------------------
// FUSED GEMM-HB + build_w. Grid = 480 hb blocks + 1024 build_w blocks,
// 128 threads each.
// ---------------------------------------------------------------------------
#define HB_NBLK 480

__global__ __launch_bounds__(128, 4) void fused_hb_kernel(
    float* __restrict__ out,
    const int* __restrict__ rels, const float* __restrict__ rel_weight)
{
    __shared__ __align__(128) char sm[3 * HB_STG];
    const int bx = blockIdx.x;
    const int t = threadIdx.x;

    if (bx >= HB_NBLK) {
        // ---------------- build_w partition ----------------
        const int id = bx - HB_NBLK;
        const int b = id >> 8;
        const int i = id & 255;

        int*   cf    = reinterpret_cast<int*>(sm);          // 32
        int*   cr    = cf + 32;                             // 32
        float* inv_f = reinterpret_cast<float*>(cr + 32);   // 32
        float* inv_r = inv_f + 32;                          // 32
        float* rw    = inv_r + 32;                          // 256

        if (t < 32) { cf[t] = 0; cr[t] = 0; }
        rw[t] = rel_weight[t];
        rw[t + 128] = rel_weight[t + 128];
        __syncthreads();

        int lf[2], lr[2];
        #pragma unroll
        for (int u = 0; u < 2; u++) {
            const int j = t + 128 * u;
            lf[u] = rels[(b * S_ + i) * S_ + j];
            lr[u] = g_relsT[(b * S_ + i) * S_ + j];
            if (lf[u] > 0) atomicAdd(&cf[lf[u]], 1);
            if (lr[u] > 0) atomicAdd(&cr[lr[u]], 1);
        }
        __syncthreads();

        if (t < 32) {
            inv_f[t] = 1.0f / (float)(cf[t] > 0 ? cf[t] : 1);
            inv_r[t] = 1.0f / (float)(cr[t] > 0 ? cr[t] : 1);
        }
        __syncthreads();

        #pragma unroll
        for (int u = 0; u < 2; u++) {
            const int j = t + 128 * u;
            float w[4] = {0.f, 0.f, 0.f, 0.f};
            if (lf[u] > 0) {
                const float s = inv_f[lf[u]];
                #pragma unroll
                for (int c = 0; c < 4; c++) w[c] += rw[lf[u] * 4 + c] * s;
            }
            if (lr[u] > 0) {
                const float s = inv_r[lr[u]];
                #pragma unroll
                for (int c = 0; c < 4; c++) w[c] += rw[(lr[u] + 32) * 4 + c] * s;
            }
            #pragma unroll
            for (int c = 0; c < 4; c++)
                g_W[((size_t)(b * S_ + i)) * KW + c * 256 + j] = __float2half(w[c]);
        }
        return;
    }

    // ---------------- hb GEMM partition ----------------
    const int n0 = (bx % 30) * 128;      // never straddles a 768-slot
    const int m0 = (bx / 30) * 64;       // global row in [0,1024)
    const int cslot = n0 / 768;
    const int o0 = n0 - cslot * 768;

    const __half* A  = g_h + (size_t)m0 * H_;
    const __half* Bm = (cslot < 4) ? g_bas + (size_t)cslot * H_ * H_ + o0
                                   : g_self + o0;

    const int lane = t & 31, wid = t >> 5;
    const int wm = wid & 1, wn = wid >> 1;
    const uint32_t smb = s2u(sm);

    float acc[2][8][4] = {};
    const int NC = 24;
    #pragma unroll 1
    for (int p = 0; p < 2; p++) {
        const int k0 = p * 32;
        const uint32_t st = smb + (uint32_t)p * HB_STG;
        ld_a32(A + k0, H_, st, t);
        ld_b32<128, HB_BP>(Bm + (size_t)k0 * H_, H_, st + HB_ABUF, t);
        asm volatile("cp.async.commit_group;" ::: "memory");
    }
    for (int c = 0; c < NC; c++) {
        asm volatile("cp.async.wait_group 1;" ::: "memory");
        __syncthreads();
        const uint32_t st = smb + (uint32_t)(c % 3) * HB_STG;
        sub_t<HB_BP, 4>(st, st + HB_ABUF, acc, lane, wm, wn);
        sub_t<HB_BP, 4>(st + 32, st + HB_ABUF + 16 * HB_BP, acc, lane, wm, wn);
        if (c + 2 < NC) {
            const int k0 = (c + 2) * 32;
            const uint32_t sn = smb + (uint32_t)((c + 2) % 3) * HB_STG;
            ld_a32(A + k0, H_, sn, t);
            ld_b32<128, HB_BP>(Bm + (size_t)k0 * H_, H_, sn + HB_ABUF, t);
        }
        asm volatile("cp.async.commit_group;" ::: "memory");
    }

    if (cslot < 4) {
        __half* dst = g_hb2 + (size_t)cslot * (B_ * S_ * H_);
        #pragma unroll
        for (int mt = 0; mt < 2; mt++)
            #pragma unroll
            for (int nv = 0; nv < 8; nv++) {
                const int row = m0 + wm * 32 + mt * 16 + (lane >> 2);
                const int col = o0 + wn * 64 + nv * 8 + (lane & 3) * 2;
                *reinterpret_cast<__half2*>(dst + (size_t)row * H_ + col) =
                    __floats2half2_rn(acc[mt][nv][0], acc[mt][nv][1]);
                *reinterpret_cast<__half2*>(dst + (size_t)(row + 8) * H_ + col) =
                    __floats2half2_rn(acc[mt][nv][2], acc[mt][nv][3]);
            }
    } else {
        #pragma unroll
        for (int mt = 0; mt < 2; mt++)
            #pragma unroll
            for (int nv = 0; nv < 8; nv++) {
                const int row = m0 + wm * 32 + mt * 16 + (lane >> 2);
                const int col = o0 + wn * 64 + nv * 8 + (lane & 3) * 2;
                float2 v0, v1;
                v0.x = acc[mt][nv][0]; v0.y = acc[mt][nv][1];
                v1.x = acc[mt][nv][2]; v1.y = acc[mt][nv][3];
                *reinterpret_cast<float2*>(out + (size_t)row * H_ + col) = v0;
                *reinterpret_cast<float2*>(out + (size_t)(row + 8) * H_ + col) = v1;
            }
    }
}

// ---------------------------------------------------------------------------
// GEMM-OUT split-K(2): out += W[:, kc*512:+512] @ hb slots {2kc, 2kc+1}.
// grid (12, 16, 2) = 384 CTAs, 128 thr, CTA 64x64, NC=16, 3-stage, red2.
// ---------------------------------------------------------------------------
__global__ __launch_bounds__(128, 6) void gemm_out_kernel(float* __restrict__ out) {
    __shared__ __align__(128) char sm[3 * OUT_STG];
    const int n0 = blockIdx.x * 64;          // col in [0,768)
    const int row0 = blockIdx.y * 64;        // global row in [0,1024)
    const int kc = blockIdx.z;               // 0..1
    const int b = row0 >> 8;

    const __half* A = g_W + (size_t)row0 * KW + kc * 512;
    const __half* Bbase = g_hb2 + (size_t)(kc * 2) * (B_ * S_ * H_)
                        + (size_t)b * S_ * H_ + n0;

    const int t = threadIdx.x, lane = t & 31, wid = t >> 5;
    const int wm = wid & 1, wn = wid >> 1;
    const uint32_t smb = s2u(sm);

    float acc[2][4][4] = {};
    const int NC = 16;
    #pragma unroll 1
    for (int p = 0; p < 2; p++) {
        const int k0 = p * 32;
        const size_t boff = (size_t)(k0 >> 8) * (B_ * S_ * H_) + (size_t)(k0 & 255) * H_;
        const uint32_t st = smb + (uint32_t)p * OUT_STG;
        ld_a32(A + k0, KW, st, t);
        ld_b32<64, OUT_BP>(Bbase + boff, H_, st + HB_ABUF, t);
        asm volatile("cp.async.commit_group;" ::: "memory");
    }
    for (int c = 0; c < NC; c++) {
        asm volatile("cp.async.wait_group 1;" ::: "memory");
        __syncthreads();
        const uint32_t st = smb + (uint32_t)(c % 3) * OUT_STG;
        sub_t<OUT_BP, 2>(st, st + HB_ABUF, acc, lane, wm, wn);
        sub_t<OUT_BP, 2>(st + 32, st + HB_ABUF + 16 * OUT_BP, acc, lane, wm, wn);
        if (c + 2 < NC) {
            const int k0 = (c + 2) * 32;
            const size_t boff = (size_t)(k0 >> 8) * (B_ * S_ * H_) + (size_t)(k0 & 255) * H_;
            const uint32_t sn = smb + (uint32_t)((c + 2) % 3) * OUT_STG;
            ld_a32(A + k0, KW, sn, t);
            ld_b32<64, OUT_BP>(Bbase + boff, H_, sn + HB_ABUF, t);
        }
        asm volatile("cp.async.commit_group;" ::: "memory");
    }

    #pragma unroll
    for (int mt = 0; mt < 2; mt++)
        #pragma unroll
        for (int nv = 0; nv < 4; nv++) {
            const int row = row0 + wm * 32 + mt * 16 + (lane >> 2);
            const int col = n0 + wn * 32 + nv * 8 + (lane & 3) * 2;
            red2(out + (size_t)row * H_ + col,       acc[mt][nv][0], acc[mt][nv][1]);
            red2(out + (size_t)(row + 8) * H_ + col, acc[mt][nv][2], acc[mt][nv][3]);
        }
}

// ---------------------------------------------------------------------------
extern "C" void kernel_launch(void* const* d_in, const int* in_sizes, int n_in,
                              void* d_out, int out_size) {
    const float* hidden     = (const float*)d_in[0]; // [4,256,768]
    const int*   rels       = (const int*)  d_in[1]; // [4,256,256]
    const float* basic      = (const float*)d_in[2]; // [4,768,768]
    const float* rel_weight = (const float*)d_in[3]; // [64,4]
    const float* self_w     = (const float*)d_in[4]; // [768,768] (out,in)
    float* out = (float*)d_out;                      // [4,256,768]

    prep_kernel<<<NB_H + NB_BAS + NB_SELF + NB_RELS, 256>>>(hidden, basic, self_w, rels);
    fused_hb_kernel<<<HB_NBLK + B_ * S_, 128>>>(out, rels, rel_weight);
    gemm_out_kernel<<<dim3(H_ / 64, (B_ * S_) / 64, 2), 128>>>(out);
}